// round 1
// baseline (speedup 1.0000x reference)
#include <cuda_runtime.h>
#include <math.h>

#define NN 50000
#define HH 8
#define DD 64
#define HD 512          // H*D
#define ALPHA 0.2f

// ---------------- scratch (static device globals; no allocation) -------------
__device__ float g_Wh [(size_t)NN * HD];   // layer-1 projected features
__device__ float g_h1 [(size_t)NN * HD];   // layer-1 output (input to layer 2)
__device__ float g_Wh2[(size_t)NN * HD];   // layer-2 projected features
__device__ float g_h2 [(size_t)NN * HD];   // layer-2 output (input to final lin)
__device__ float g_f1 [NN * HH];
__device__ float g_f2 [NN * HH];
__device__ int   g_rowptr[NN + 1];
__device__ float g_W1c[256 * HD];          // packed [F, H*D]
__device__ float g_W2c[512 * HD];

// ---------------- weight packing: [H,F,D] -> [F, H*D] ------------------------
__global__ void pack_w(const float* __restrict__ W, float* __restrict__ out, int F) {
    int i = blockIdx.x * blockDim.x + threadIdx.x;
    int total = F * HD;
    if (i >= total) return;
    int f = i / HD;
    int n = i - f * HD;
    int h = n >> 6;
    int d = n & 63;
    out[i] = W[((size_t)h * F + f) * DD + d];
}

// ---------------- CSR rowptr from sorted edge_src ----------------------------
__global__ void build_rowptr(const int* __restrict__ src, int E) {
    int i = blockIdx.x * blockDim.x + threadIdx.x;
    if (i >= E) return;
    int s = src[i];
    if (i == 0) {
        for (int u = 0; u <= s; u++) g_rowptr[u] = 0;
    } else {
        int p = src[i - 1];
        for (int u = p + 1; u <= s; u++) g_rowptr[u] = i;
    }
    if (i == E - 1) {
        for (int u = s + 1; u <= NN; u++) g_rowptr[u] = E;
    }
}

// ---------------- tiled fp32 GEMM: C[M,N] = A[M,K] @ B[K,N] (+bias) ----------
// BM=64, BN=64, BK=16, 256 threads, 4x4 per thread.
__global__ __launch_bounds__(256)
void gemm_kernel(const float* __restrict__ A, const float* __restrict__ B,
                 float* __restrict__ C, const float* __restrict__ bias,
                 int M, int K, int N) {
    __shared__ float As[16][64];
    __shared__ float Bs[16][64];

    int t  = threadIdx.x;
    int bm = blockIdx.y * 64;
    int bn = blockIdx.x * 64;
    int ty = t >> 4;           // 0..15 (M dir)
    int tx = t & 15;           // 0..15 (N dir)

    int arow = t >> 2;         // 0..63
    int acol = (t & 3) << 2;   // 0,4,8,12
    int brow = t >> 4;         // 0..15
    int bcol = (t & 15) << 2;  // 0..60

    int a_grow = bm + arow;
    bool a_ok = a_grow < M;

    float acc[4][4];
#pragma unroll
    for (int i = 0; i < 4; i++)
#pragma unroll
        for (int j = 0; j < 4; j++) acc[i][j] = 0.f;

    for (int k0 = 0; k0 < K; k0 += 16) {
        float4 av = make_float4(0.f, 0.f, 0.f, 0.f);
        if (a_ok) av = *(const float4*)(A + (size_t)a_grow * K + k0 + acol);
        As[acol + 0][arow] = av.x;
        As[acol + 1][arow] = av.y;
        As[acol + 2][arow] = av.z;
        As[acol + 3][arow] = av.w;
        float4 bv = *(const float4*)(B + (size_t)(k0 + brow) * N + bn + bcol);
        *(float4*)&Bs[brow][bcol] = bv;
        __syncthreads();
#pragma unroll
        for (int k = 0; k < 16; k++) {
            float4 a4 = *(const float4*)&As[k][ty << 2];
            float4 b4 = *(const float4*)&Bs[k][tx << 2];
            float a[4] = {a4.x, a4.y, a4.z, a4.w};
            float b[4] = {b4.x, b4.y, b4.z, b4.w};
#pragma unroll
            for (int i = 0; i < 4; i++)
#pragma unroll
                for (int j = 0; j < 4; j++) acc[i][j] = fmaf(a[i], b[j], acc[i][j]);
        }
        __syncthreads();
    }

    float bb[4] = {0.f, 0.f, 0.f, 0.f};
    if (bias) {
#pragma unroll
        for (int j = 0; j < 4; j++) bb[j] = bias[bn + (tx << 2) + j];
    }
#pragma unroll
    for (int i = 0; i < 4; i++) {
        int row = bm + (ty << 2) + i;
        if (row >= M) continue;
        float* cp = C + (size_t)row * N + bn + (tx << 2);
        float4 o = make_float4(acc[i][0] + bb[0], acc[i][1] + bb[1],
                               acc[i][2] + bb[2], acc[i][3] + bb[3]);
        *(float4*)cp = o;
    }
}

// ---------------- attention scores f1[n,h] = Wh[n,h,:]·a_s[h,:] --------------
__global__ void fscore_kernel(const float* __restrict__ Wh,
                              const float* __restrict__ a_s,
                              const float* __restrict__ a_d,
                              float* __restrict__ f1, float* __restrict__ f2) {
    int i = blockIdx.x * blockDim.x + threadIdx.x;   // i = n*8 + h
    if (i >= NN * HH) return;
    int h = i & 7;
    const float4* w  = (const float4*)(Wh + (size_t)i * DD);  // n*512 + h*64 == i*64
    const float4* s4 = (const float4*)(a_s + h * DD);
    const float4* d4 = (const float4*)(a_d + h * DD);
    float s1 = 0.f, s2 = 0.f;
#pragma unroll
    for (int j = 0; j < 16; j++) {
        float4 wv = w[j];
        float4 x1 = s4[j];
        float4 x2 = d4[j];
        s1 += wv.x * x1.x + wv.y * x1.y + wv.z * x1.z + wv.w * x1.w;
        s2 += wv.x * x2.x + wv.y * x2.y + wv.z * x2.z + wv.w * x2.w;
    }
    f1[i] = s1;
    f2[i] = s2;
}

// ---------------- per-node softmax + SPMM + ELU ------------------------------
// One block (128 threads) per node. Thread owns (head h = t>>4, dims d0..d0+3).
__device__ __forceinline__ float elu_f(float x) {
    return x > 0.f ? x : (__expf(x) - 1.f);
}

__global__ __launch_bounds__(128)
void aggregate_kernel(const int* __restrict__ dst,
                      const float* __restrict__ Wh,
                      const float* __restrict__ f1,
                      const float* __restrict__ f2,
                      float* __restrict__ out) {
    int u  = blockIdx.x;
    int t  = threadIdx.x;
    int h  = t >> 4;
    int d0 = (t & 15) << 2;

    int beg = g_rowptr[u];
    int end = g_rowptr[u + 1];

    float fu = f1[u * HH + h];

    // pass 1: max of leaky scores (redundant across the 16 threads of a head; cheap)
    float m = -1e30f;
    for (int e = beg; e < end; e++) {
        int v = __ldg(&dst[e]);
        float x = fu + __ldg(&f2[v * HH + h]);
        x = x > 0.f ? x : ALPHA * x;
        m = fmaxf(m, x);
    }

    // pass 2: exp-sum + weighted gather-accumulate
    float s = 0.f;
    float4 acc = make_float4(0.f, 0.f, 0.f, 0.f);
    for (int e = beg; e < end; e++) {
        int v = __ldg(&dst[e]);
        float x = fu + __ldg(&f2[v * HH + h]);
        x = x > 0.f ? x : ALPHA * x;
        float p = __expf(x - m);
        s += p;
        float4 w = *(const float4*)(Wh + (size_t)v * HD + h * DD + d0);
        acc.x = fmaf(p, w.x, acc.x);
        acc.y = fmaf(p, w.y, acc.y);
        acc.z = fmaf(p, w.z, acc.z);
        acc.w = fmaf(p, w.w, acc.w);
    }

    float inv = (end > beg) ? (1.f / s) : 0.f;
    float4 o;
    o.x = elu_f(acc.x * inv);
    o.y = elu_f(acc.y * inv);
    o.z = elu_f(acc.z * inv);
    o.w = elu_f(acc.w * inv);
    *(float4*)(out + (size_t)u * HD + h * DD + d0) = o;
}

// ---------------- launch ------------------------------------------------------
extern "C" void kernel_launch(void* const* d_in, const int* in_sizes, int n_in,
                              void* d_out, int out_size) {
    const float* x       = (const float*)d_in[0];
    const int*   src     = (const int*)  d_in[1];
    const int*   dst     = (const int*)  d_in[2];
    const float* W1      = (const float*)d_in[3];
    const float* a_src1  = (const float*)d_in[4];
    const float* a_dst1  = (const float*)d_in[5];
    const float* W2      = (const float*)d_in[6];
    const float* a_src2  = (const float*)d_in[7];
    const float* a_dst2  = (const float*)d_in[8];
    const float* lin_W   = (const float*)d_in[9];
    const float* lin_b   = (const float*)d_in[10];
    float* out = (float*)d_out;

    int E = in_sizes[1];

    float *p_Wh, *p_h1, *p_Wh2, *p_h2, *p_f1, *p_f2, *p_W1c, *p_W2c;
    cudaGetSymbolAddress((void**)&p_Wh,  g_Wh);
    cudaGetSymbolAddress((void**)&p_h1,  g_h1);
    cudaGetSymbolAddress((void**)&p_Wh2, g_Wh2);
    cudaGetSymbolAddress((void**)&p_h2,  g_h2);
    cudaGetSymbolAddress((void**)&p_f1,  g_f1);
    cudaGetSymbolAddress((void**)&p_f2,  g_f2);
    cudaGetSymbolAddress((void**)&p_W1c, g_W1c);
    cudaGetSymbolAddress((void**)&p_W2c, g_W2c);

    // pack weights + build CSR
    pack_w<<<(256 * HD + 255) / 256, 256>>>(W1, p_W1c, 256);
    pack_w<<<(512 * HD + 255) / 256, 256>>>(W2, p_W2c, 512);
    build_rowptr<<<(E + 255) / 256, 256>>>(src, E);

    dim3 g1(HD / 64, (NN + 63) / 64);

    // ---- layer 1 ----
    gemm_kernel<<<g1, 256>>>(x, p_W1c, p_Wh, nullptr, NN, 256, HD);
    fscore_kernel<<<(NN * HH + 255) / 256, 256>>>(p_Wh, a_src1, a_dst1, p_f1, p_f2);
    aggregate_kernel<<<NN, 128>>>(dst, p_Wh, p_f1, p_f2, p_h1);

    // ---- layer 2 ----
    gemm_kernel<<<g1, 256>>>(p_h1, p_W2c, p_Wh2, nullptr, NN, 512, HD);
    fscore_kernel<<<(NN * HH + 255) / 256, 256>>>(p_Wh2, a_src2, a_dst2, p_f1, p_f2);
    aggregate_kernel<<<NN, 128>>>(dst, p_Wh2, p_f1, p_f2, p_h2);

    // ---- final linear (with bias) ----
    dim3 g3(64 / 64, (NN + 63) / 64);
    gemm_kernel<<<g3, 256>>>(p_h2, lin_W, out, lin_b, NN, 512, 64);
}

// round 2
// speedup vs baseline: 1.1484x; 1.1484x over previous
#include <cuda_runtime.h>
#include <math.h>

#define NN 50000
#define HH 8
#define DD 64
#define HD 512          // H*D
#define ALPHA 0.2f

// ---------------- scratch (static device globals; no allocation) -------------
__device__ float g_Wh [(size_t)NN * HD];
__device__ float g_h1 [(size_t)NN * HD];
__device__ float g_Wh2[(size_t)NN * HD];
__device__ float g_h2 [(size_t)NN * HD];
__device__ float g_f1 [NN * HH];
__device__ float g_f2 [NN * HH];
__device__ int   g_rowptr[NN + 1];
__device__ float g_W1c[256 * HD];
__device__ float g_W2c[512 * HD];

// ---------------- weight packing: [H,F,D] -> [F, H*D] ------------------------
__global__ void pack_w(const float* __restrict__ W, float* __restrict__ out, int F) {
    int i = blockIdx.x * blockDim.x + threadIdx.x;
    int total = F * HD;
    if (i >= total) return;
    int f = i / HD;
    int n = i - f * HD;
    int h = n >> 6;
    int d = n & 63;
    out[i] = W[((size_t)h * F + f) * DD + d];
}

// ---------------- CSR rowptr from sorted edge_src ----------------------------
__global__ void build_rowptr(const int* __restrict__ src, int E) {
    int i = blockIdx.x * blockDim.x + threadIdx.x;
    if (i >= E) return;
    int s = src[i];
    if (i == 0) {
        for (int u = 0; u <= s; u++) g_rowptr[u] = 0;
    } else {
        int p = src[i - 1];
        for (int u = p + 1; u <= s; u++) g_rowptr[u] = i;
    }
    if (i == E - 1) {
        for (int u = s + 1; u <= NN; u++) g_rowptr[u] = E;
    }
}

// ---------------- 128x128x16 fp32 GEMM, 8x8 per-thread -----------------------
// C[M,N] = A[M,K] @ B[K,N].  Requires N % 128 == 0, K % 16 == 0.
__global__ __launch_bounds__(256)
void gemm128(const float* __restrict__ A, const float* __restrict__ B,
             float* __restrict__ C, int M, int K, int N) {
    __shared__ float As[16][128];
    __shared__ float Bs[16][128];

    const int t  = threadIdx.x;
    const int bm = blockIdx.y * 128;
    const int bn = blockIdx.x * 128;
    const int tx = t & 15;          // 0..15  (N dir)
    const int ty = t >> 4;          // 0..15  (M dir)

    // global-load assignments (2 float4 each for A-tile and B-tile)
    // A tile: 128 rows x 16 cols = 512 float4; idx i: row=i>>2, col4=i&3
    const int a_r0 = t >> 2,          a_c0 = (t & 3) << 2;
    const int a_r1 = (t + 256) >> 2,  a_c1 = a_c0;   // same col pattern
    // B tile: 16 rows x 128 cols = 512 float4; idx i: row=i>>5, col4=i&31
    const int b_r0 = t >> 5,          b_c0 = (t & 31) << 2;
    const int b_r1 = (t + 256) >> 5,  b_c1 = b_c0;

    const bool a_ok0 = (bm + a_r0) < M;
    const bool a_ok1 = (bm + a_r1) < M;

    float acc[8][8];
#pragma unroll
    for (int i = 0; i < 8; i++)
#pragma unroll
        for (int j = 0; j < 8; j++) acc[i][j] = 0.f;

    float4 pa0, pa1, pb0, pb1;

    // prologue: load tile 0 into registers
    {
        pa0 = a_ok0 ? *(const float4*)(A + (size_t)(bm + a_r0) * K + a_c0)
                    : make_float4(0.f, 0.f, 0.f, 0.f);
        pa1 = a_ok1 ? *(const float4*)(A + (size_t)(bm + a_r1) * K + a_c1)
                    : make_float4(0.f, 0.f, 0.f, 0.f);
        pb0 = *(const float4*)(B + (size_t)b_r0 * N + bn + b_c0);
        pb1 = *(const float4*)(B + (size_t)b_r1 * N + bn + b_c1);
    }

    const int nk = K >> 4;
    for (int kt = 0; kt < nk; kt++) {
        // store current regs -> smem
        As[a_c0 + 0][a_r0] = pa0.x;
        As[a_c0 + 1][a_r0] = pa0.y;
        As[a_c0 + 2][a_r0] = pa0.z;
        As[a_c0 + 3][a_r0] = pa0.w;
        As[a_c1 + 0][a_r1] = pa1.x;
        As[a_c1 + 1][a_r1] = pa1.y;
        As[a_c1 + 2][a_r1] = pa1.z;
        As[a_c1 + 3][a_r1] = pa1.w;
        *(float4*)&Bs[b_r0][b_c0] = pb0;
        *(float4*)&Bs[b_r1][b_c1] = pb1;
        __syncthreads();

        // prefetch next tile into registers
        if (kt + 1 < nk) {
            int k0 = (kt + 1) << 4;
            pa0 = a_ok0 ? *(const float4*)(A + (size_t)(bm + a_r0) * K + k0 + a_c0)
                        : make_float4(0.f, 0.f, 0.f, 0.f);
            pa1 = a_ok1 ? *(const float4*)(A + (size_t)(bm + a_r1) * K + k0 + a_c1)
                        : make_float4(0.f, 0.f, 0.f, 0.f);
            pb0 = *(const float4*)(B + (size_t)(k0 + b_r0) * N + bn + b_c0);
            pb1 = *(const float4*)(B + (size_t)(k0 + b_r1) * N + bn + b_c1);
        }

        // compute 16 k-steps
#pragma unroll
        for (int k = 0; k < 16; k++) {
            float4 a0 = *(const float4*)&As[k][ty << 2];
            float4 a1 = *(const float4*)&As[k][64 + (ty << 2)];
            float4 b0 = *(const float4*)&Bs[k][tx << 2];
            float4 b1 = *(const float4*)&Bs[k][64 + (tx << 2)];
            float av[8] = {a0.x, a0.y, a0.z, a0.w, a1.x, a1.y, a1.z, a1.w};
            float bv[8] = {b0.x, b0.y, b0.z, b0.w, b1.x, b1.y, b1.z, b1.w};
#pragma unroll
            for (int i = 0; i < 8; i++)
#pragma unroll
                for (int j = 0; j < 8; j++)
                    acc[i][j] = fmaf(av[i], bv[j], acc[i][j]);
        }
        __syncthreads();
    }

    // epilogue: C rows {bm + ty*4 + i, bm + 64 + ty*4 + i}, cols likewise
#pragma unroll
    for (int ih = 0; ih < 2; ih++) {
#pragma unroll
        for (int i = 0; i < 4; i++) {
            int row = bm + ih * 64 + (ty << 2) + i;
            if (row >= M) continue;
            float* cp = C + (size_t)row * N + bn;
            *(float4*)(cp + (tx << 2))      = make_float4(acc[ih*4+i][0], acc[ih*4+i][1],
                                                          acc[ih*4+i][2], acc[ih*4+i][3]);
            *(float4*)(cp + 64 + (tx << 2)) = make_float4(acc[ih*4+i][4], acc[ih*4+i][5],
                                                          acc[ih*4+i][6], acc[ih*4+i][7]);
        }
    }
}

// ---------------- small GEMM (final linear, N=64) ----------------------------
__global__ __launch_bounds__(256)
void gemm_kernel(const float* __restrict__ A, const float* __restrict__ B,
                 float* __restrict__ C, const float* __restrict__ bias,
                 int M, int K, int N) {
    __shared__ float As[16][64];
    __shared__ float Bs[16][64];

    int t  = threadIdx.x;
    int bm = blockIdx.y * 64;
    int bn = blockIdx.x * 64;
    int ty = t >> 4;
    int tx = t & 15;

    int arow = t >> 2;
    int acol = (t & 3) << 2;
    int brow = t >> 4;
    int bcol = (t & 15) << 2;

    int a_grow = bm + arow;
    bool a_ok = a_grow < M;

    float acc[4][4];
#pragma unroll
    for (int i = 0; i < 4; i++)
#pragma unroll
        for (int j = 0; j < 4; j++) acc[i][j] = 0.f;

    for (int k0 = 0; k0 < K; k0 += 16) {
        float4 av = make_float4(0.f, 0.f, 0.f, 0.f);
        if (a_ok) av = *(const float4*)(A + (size_t)a_grow * K + k0 + acol);
        As[acol + 0][arow] = av.x;
        As[acol + 1][arow] = av.y;
        As[acol + 2][arow] = av.z;
        As[acol + 3][arow] = av.w;
        float4 bv = *(const float4*)(B + (size_t)(k0 + brow) * N + bn + bcol);
        *(float4*)&Bs[brow][bcol] = bv;
        __syncthreads();
#pragma unroll
        for (int k = 0; k < 16; k++) {
            float4 a4 = *(const float4*)&As[k][ty << 2];
            float4 b4 = *(const float4*)&Bs[k][tx << 2];
            float a[4] = {a4.x, a4.y, a4.z, a4.w};
            float b[4] = {b4.x, b4.y, b4.z, b4.w};
#pragma unroll
            for (int i = 0; i < 4; i++)
#pragma unroll
                for (int j = 0; j < 4; j++) acc[i][j] = fmaf(a[i], b[j], acc[i][j]);
        }
        __syncthreads();
    }

    float bb[4] = {0.f, 0.f, 0.f, 0.f};
    if (bias) {
#pragma unroll
        for (int j = 0; j < 4; j++) bb[j] = bias[bn + (tx << 2) + j];
    }
#pragma unroll
    for (int i = 0; i < 4; i++) {
        int row = bm + (ty << 2) + i;
        if (row >= M) continue;
        float* cp = C + (size_t)row * N + bn + (tx << 2);
        float4 o = make_float4(acc[i][0] + bb[0], acc[i][1] + bb[1],
                               acc[i][2] + bb[2], acc[i][3] + bb[3]);
        *(float4*)cp = o;
    }
}

// ---------------- attention scores -------------------------------------------
__global__ void fscore_kernel(const float* __restrict__ Wh,
                              const float* __restrict__ a_s,
                              const float* __restrict__ a_d,
                              float* __restrict__ f1, float* __restrict__ f2) {
    int i = blockIdx.x * blockDim.x + threadIdx.x;   // i = n*8 + h
    if (i >= NN * HH) return;
    int h = i & 7;
    const float4* w  = (const float4*)(Wh + (size_t)i * DD);
    const float4* s4 = (const float4*)(a_s + h * DD);
    const float4* d4 = (const float4*)(a_d + h * DD);
    float s1 = 0.f, s2 = 0.f;
#pragma unroll
    for (int j = 0; j < 16; j++) {
        float4 wv = w[j];
        float4 x1 = s4[j];
        float4 x2 = d4[j];
        s1 += wv.x * x1.x + wv.y * x1.y + wv.z * x1.z + wv.w * x1.w;
        s2 += wv.x * x2.x + wv.y * x2.y + wv.z * x2.z + wv.w * x2.w;
    }
    f1[i] = s1;
    f2[i] = s2;
}

// ---------------- per-node softmax + SPMM + ELU ------------------------------
__device__ __forceinline__ float elu_f(float x) {
    return x > 0.f ? x : (__expf(x) - 1.f);
}

__global__ __launch_bounds__(128)
void aggregate_kernel(const int* __restrict__ dst,
                      const float* __restrict__ Wh,
                      const float* __restrict__ f1,
                      const float* __restrict__ f2,
                      float* __restrict__ out) {
    int u  = blockIdx.x;
    int t  = threadIdx.x;
    int h  = t >> 4;
    int d0 = (t & 15) << 2;

    int beg = g_rowptr[u];
    int end = g_rowptr[u + 1];

    float fu = f1[u * HH + h];

    float m = -1e30f;
    for (int e = beg; e < end; e++) {
        int v = __ldg(&dst[e]);
        float x = fu + __ldg(&f2[v * HH + h]);
        x = x > 0.f ? x : ALPHA * x;
        m = fmaxf(m, x);
    }

    float s = 0.f;
    float4 acc = make_float4(0.f, 0.f, 0.f, 0.f);
    for (int e = beg; e < end; e++) {
        int v = __ldg(&dst[e]);
        float x = fu + __ldg(&f2[v * HH + h]);
        x = x > 0.f ? x : ALPHA * x;
        float p = __expf(x - m);
        s += p;
        float4 w = *(const float4*)(Wh + (size_t)v * HD + h * DD + d0);
        acc.x = fmaf(p, w.x, acc.x);
        acc.y = fmaf(p, w.y, acc.y);
        acc.z = fmaf(p, w.z, acc.z);
        acc.w = fmaf(p, w.w, acc.w);
    }

    float inv = (end > beg) ? (1.f / s) : 0.f;
    float4 o;
    o.x = elu_f(acc.x * inv);
    o.y = elu_f(acc.y * inv);
    o.z = elu_f(acc.z * inv);
    o.w = elu_f(acc.w * inv);
    *(float4*)(out + (size_t)u * HD + h * DD + d0) = o;
}

// ---------------- launch ------------------------------------------------------
extern "C" void kernel_launch(void* const* d_in, const int* in_sizes, int n_in,
                              void* d_out, int out_size) {
    const float* x       = (const float*)d_in[0];
    const int*   src     = (const int*)  d_in[1];
    const int*   dst     = (const int*)  d_in[2];
    const float* W1      = (const float*)d_in[3];
    const float* a_src1  = (const float*)d_in[4];
    const float* a_dst1  = (const float*)d_in[5];
    const float* W2      = (const float*)d_in[6];
    const float* a_src2  = (const float*)d_in[7];
    const float* a_dst2  = (const float*)d_in[8];
    const float* lin_W   = (const float*)d_in[9];
    const float* lin_b   = (const float*)d_in[10];
    float* out = (float*)d_out;

    int E = in_sizes[1];

    float *p_Wh, *p_h1, *p_Wh2, *p_h2, *p_f1, *p_f2, *p_W1c, *p_W2c;
    cudaGetSymbolAddress((void**)&p_Wh,  g_Wh);
    cudaGetSymbolAddress((void**)&p_h1,  g_h1);
    cudaGetSymbolAddress((void**)&p_Wh2, g_Wh2);
    cudaGetSymbolAddress((void**)&p_h2,  g_h2);
    cudaGetSymbolAddress((void**)&p_f1,  g_f1);
    cudaGetSymbolAddress((void**)&p_f2,  g_f2);
    cudaGetSymbolAddress((void**)&p_W1c, g_W1c);
    cudaGetSymbolAddress((void**)&p_W2c, g_W2c);

    pack_w<<<(256 * HD + 255) / 256, 256>>>(W1, p_W1c, 256);
    pack_w<<<(512 * HD + 255) / 256, 256>>>(W2, p_W2c, 512);
    build_rowptr<<<(E + 255) / 256, 256>>>(src, E);

    dim3 gBig(HD / 128, (NN + 127) / 128);   // (4, 391)

    // ---- layer 1 ----
    gemm128<<<gBig, 256>>>(x, p_W1c, p_Wh, NN, 256, HD);
    fscore_kernel<<<(NN * HH + 255) / 256, 256>>>(p_Wh, a_src1, a_dst1, p_f1, p_f2);
    aggregate_kernel<<<NN, 128>>>(dst, p_Wh, p_f1, p_f2, p_h1);

    // ---- layer 2 ----
    gemm128<<<gBig, 256>>>(p_h1, p_W2c, p_Wh2, NN, 512, HD);
    fscore_kernel<<<(NN * HH + 255) / 256, 256>>>(p_Wh2, a_src2, a_dst2, p_f1, p_f2);
    aggregate_kernel<<<NN, 128>>>(dst, p_Wh2, p_f1, p_f2, p_h2);

    // ---- final linear (with bias), N=64 ----
    dim3 g3(1, (NN + 63) / 64);
    gemm_kernel<<<g3, 256>>>(p_h2, lin_W, out, lin_b, NN, 512, 64);
}

// round 4
// speedup vs baseline: 1.9658x; 1.7118x over previous
#include <cuda_runtime.h>
#include <cuda_bf16.h>
#include <cstdint>
#include <math.h>

#define NN 50000
#define NPAD 50048            // 391 * 128
#define HH 8
#define DD 64
#define HD 512
#define ALPHA 0.2f

#define K3_L1 768             // 3 * 256
#define K3_L2 1536            // 3 * 512

// ---------------- scratch (static device globals; zero-initialized) ----------
__device__ __align__(16) __nv_bfloat16 g_A1[(size_t)NPAD * K3_L1];
__device__ __align__(16) __nv_bfloat16 g_A2[(size_t)NPAD * K3_L2];
__device__ __align__(16) __nv_bfloat16 g_AL[(size_t)NPAD * K3_L2];
__device__ __align__(16) __nv_bfloat16 g_B1[512 * K3_L1];
__device__ __align__(16) __nv_bfloat16 g_B2[512 * K3_L2];
__device__ __align__(16) __nv_bfloat16 g_BL[64 * K3_L2];
__device__ __align__(16) float g_Wh[(size_t)NN * HD];
__device__ __align__(16) float g_f1[NN * HH];
__device__ __align__(16) float g_f2[NN * HH];
__device__ int g_rowptr[NN + 1];

// ---------------- PTX helpers (baseline sm_100 features only) -----------------
__device__ __forceinline__ uint32_t smem_u32(const void* p) {
    uint32_t a;
    asm("{ .reg .u64 t; cvta.to.shared.u64 t, %1; cvt.u32.u64 %0, t; }" : "=r"(a) : "l"(p));
    return a;
}
__device__ __forceinline__ void cp16(uint32_t dst, const void* src) {
    asm volatile("cp.async.cg.shared.global [%0], [%1], 16;" :: "r"(dst), "l"(src));
}
#define CP_COMMIT() asm volatile("cp.async.commit_group;" ::: "memory")
template<int N>
__device__ __forceinline__ void cp_wait() {
    asm volatile("cp.async.wait_group %0;" :: "n"(N) : "memory");
}
__device__ __forceinline__ void ldm_x4(uint32_t& r0, uint32_t& r1, uint32_t& r2, uint32_t& r3,
                                       uint32_t addr) {
    asm volatile("ldmatrix.sync.aligned.m8n8.x4.shared.b16 {%0,%1,%2,%3}, [%4];"
                 : "=r"(r0), "=r"(r1), "=r"(r2), "=r"(r3) : "r"(addr));
}
__device__ __forceinline__ void mma16816(float* c, const uint32_t* a, const uint32_t* b) {
    asm volatile("mma.sync.aligned.m16n8k16.row.col.f32.bf16.bf16.f32 "
                 "{%0,%1,%2,%3}, {%4,%5,%6,%7}, {%8,%9}, {%0,%1,%2,%3};"
                 : "+f"(c[0]), "+f"(c[1]), "+f"(c[2]), "+f"(c[3])
                 : "r"(a[0]), "r"(a[1]), "r"(a[2]), "r"(a[3]), "r"(b[0]), "r"(b[1]));
}
#define SWZ(x) ((x) ^ (((x) >> 3) & 0x70))

// ---------------- hi/lo split helpers ----------------------------------------
__device__ __forceinline__ void hl_split(float v, __nv_bfloat16& h, __nv_bfloat16& l) {
    h = __float2bfloat16(v);
    l = __float2bfloat16(v - __bfloat162float(h));
}

// ---------------- mma.sync GEMM: C[M,N] = A'[M,K3] * B'[N,K3]^T ---------------
// A' [Mpad,K3] bf16 row-major, B' [Ncols,K3] bf16 row-major (both K-major).
// Block 128 x N_TILE, 8 warps (2x4), warp tile 64 x (N_TILE/4).
// K chunks of 64, double-buffered cp.async, SW128-swizzled smem.
template<int N_TILE>
__global__ __launch_bounds__(256)
void mma_gemm(const __nv_bfloat16* __restrict__ A, const __nv_bfloat16* __restrict__ B,
              float* __restrict__ C, const float* __restrict__ bias,
              int M, int K3, int ldC)
{
    constexpr int WN = N_TILE / 4;     // warp N extent (32 or 16)
    constexpr int NF = WN / 8;         // n8 fragments per warp (4 or 2)
    constexpr int NG = NF / 2;         // n16 ldmatrix groups (2 or 1)
    constexpr int ABUF = 128 * 128;    // 16 KB (128 rows x 128B)
    constexpr int BBUF = N_TILE * 128;
    constexpr int NB = N_TILE / 32;    // B cp.async iters per thread

    extern __shared__ __align__(1024) char smem[];
    const uint32_t sb = smem_u32(smem);

    const int t = threadIdx.x, lane = t & 31, wid = t >> 5;
    const int warp_m = wid >> 2, warp_n = wid & 3;
    const int bm = blockIdx.y * 128, bn = blockIdx.x * N_TILE;

    const char* gA = (const char*)(A + (size_t)bm * K3);
    const char* gB = (const char*)(B + (size_t)bn * K3);
    const size_t strA = (size_t)K3 * 2;   // bytes per row

    // per-thread cp.async coordinates
    const int ld_row = t >> 3;            // 0..31 step (x8 rows per 256 thr? no: u>>3)
    (void)ld_row;

    float acc[4][NF][4];
#pragma unroll
    for (int i = 0; i < 4; i++)
#pragma unroll
        for (int j = 0; j < NF; j++)
#pragma unroll
            for (int v = 0; v < 4; v++) acc[i][j][v] = 0.f;

    const int nk = K3 >> 6;

    auto issue = [&](int kt, int buf) {
        const size_t koff = (size_t)kt * 128;
#pragma unroll
        for (int i = 0; i < 4; i++) {                    // A: 1024 16B units
            int u = t + i * 256;
            int row = u >> 3, sub = (u & 7) << 4;
            uint32_t dst = sb + buf * ABUF + SWZ((uint32_t)(row * 128 + sub));
            cp16(dst, gA + (size_t)row * strA + koff + sub);
        }
#pragma unroll
        for (int i = 0; i < NB; i++) {                   // B: N_TILE*8 units
            int u = t + i * 256;
            int row = u >> 3, sub = (u & 7) << 4;
            uint32_t dst = sb + 2 * ABUF + buf * BBUF + SWZ((uint32_t)(row * 128 + sub));
            cp16(dst, gB + (size_t)row * strA + koff + sub);
        }
        CP_COMMIT();
    };

    issue(0, 0);

    // ldmatrix lane coordinates
    const int mat = lane >> 3, lr = lane & 7;
    // A: mat0:(r0,k0) mat1:(r8,k0) mat2:(r0,k8) mat3:(r8,k8)
    const int a_roff = (mat & 1) * 8, a_koff = (mat >> 1) * 16;
    // B: mat0:(n0,k0) mat1:(n0,k8) mat2:(n8,k0) mat3:(n8,k8)
    const int b_roff = (mat >> 1) * 8, b_koff = (mat & 1) * 16;

    for (int kt = 0; kt < nk; kt++) {
        const int buf = kt & 1;
        if (kt + 1 < nk) { issue(kt + 1, buf ^ 1); cp_wait<1>(); }
        else            { cp_wait<0>(); }
        __syncthreads();

        const uint32_t abase = sb + buf * ABUF;
        const uint32_t bbase = sb + 2 * ABUF + buf * BBUF;

#pragma unroll
        for (int s = 0; s < 4; s++) {                    // 4 k16 steps per chunk
            uint32_t a[4][4];
#pragma unroll
            for (int i = 0; i < 4; i++) {
                int row = warp_m * 64 + i * 16 + a_roff + lr;
                uint32_t addr = abase + SWZ((uint32_t)(row * 128 + s * 32 + a_koff));
                ldm_x4(a[i][0], a[i][1], a[i][2], a[i][3], addr);
            }
            uint32_t b[NF][2];
#pragma unroll
            for (int g = 0; g < NG; g++) {
                int row = warp_n * WN + g * 16 + b_roff + lr;
                uint32_t addr = bbase + SWZ((uint32_t)(row * 128 + s * 32 + b_koff));
                uint32_t r0, r1, r2, r3;
                ldm_x4(r0, r1, r2, r3, addr);
                b[2 * g][0] = r0; b[2 * g][1] = r1;
                b[2 * g + 1][0] = r2; b[2 * g + 1][1] = r3;
            }
#pragma unroll
            for (int i = 0; i < 4; i++)
#pragma unroll
                for (int j = 0; j < NF; j++)
                    mma16816(acc[i][j], a[i], b[j]);
        }
        __syncthreads();
    }

    // epilogue: thread holds rows (t/4, +8) cols (t%4)*2,+1 per fragment
    const int er = lane >> 2, ec = (lane & 3) * 2;
#pragma unroll
    for (int i = 0; i < 4; i++) {
        int r0 = bm + warp_m * 64 + i * 16 + er;
        int r1 = r0 + 8;
#pragma unroll
        for (int j = 0; j < NF; j++) {
            int cn = bn + warp_n * WN + j * 8 + ec;
            float b0 = 0.f, b1 = 0.f;
            if (bias) { b0 = bias[cn]; b1 = bias[cn + 1]; }
            if (r0 < M) {
                float2 o = make_float2(acc[i][j][0] + b0, acc[i][j][1] + b1);
                *(float2*)(C + (size_t)r0 * ldC + cn) = o;
            }
            if (r1 < M) {
                float2 o = make_float2(acc[i][j][2] + b0, acc[i][j][3] + b1);
                *(float2*)(C + (size_t)r1 * ldC + cn) = o;
            }
        }
    }
}

// ---------------- input conversion: x -> A1' = [hi | lo | hi] ----------------
__global__ void conv_x(const float* __restrict__ X, __nv_bfloat16* __restrict__ A1) {
    int i = blockIdx.x * blockDim.x + threadIdx.x;  // over NN*64 (4 cols each)
    if (i >= NN * 64) return;
    int m = i >> 6, k = (i & 63) << 2;
    float4 v = *(const float4*)(X + (size_t)m * 256 + k);
    __nv_bfloat16 hx, hy, hz, hw, lx, ly, lz, lw;
    hl_split(v.x, hx, lx); hl_split(v.y, hy, ly);
    hl_split(v.z, hz, lz); hl_split(v.w, hw, lw);
    __nv_bfloat16* p = A1 + (size_t)m * K3_L1 + k;
    *(__nv_bfloat162*)(p)            = __halves2bfloat162(hx, hy);
    *(__nv_bfloat162*)(p + 2)        = __halves2bfloat162(hz, hw);
    *(__nv_bfloat162*)(p + 256)      = __halves2bfloat162(lx, ly);
    *(__nv_bfloat162*)(p + 258)      = __halves2bfloat162(lz, lw);
    *(__nv_bfloat162*)(p + 512)      = __halves2bfloat162(hx, hy);
    *(__nv_bfloat162*)(p + 514)      = __halves2bfloat162(hz, hw);
}

// ---------------- weight conversion: W[H,F,D] -> Bt'[512, 3F] = [hi|hi|lo] ---
__global__ void conv_w(const float* __restrict__ W, __nv_bfloat16* __restrict__ Bt, int F) {
    int i = blockIdx.x * blockDim.x + threadIdx.x;  // over 512*F
    if (i >= 512 * F) return;
    int n = i / F, k = i - n * F;
    int h = n >> 6, d = n & 63;
    float w = W[((size_t)h * F + k) * 64 + d];
    __nv_bfloat16 hi, lo; hl_split(w, hi, lo);
    size_t K3 = 3 * (size_t)F;
    Bt[(size_t)n * K3 + k]         = hi;
    Bt[(size_t)n * K3 + F + k]     = hi;
    Bt[(size_t)n * K3 + 2 * F + k] = lo;
}

// lin_W [512, 64] -> BtL [64, 1536]
__global__ void conv_linw(const float* __restrict__ W, __nv_bfloat16* __restrict__ Bt) {
    int i = blockIdx.x * blockDim.x + threadIdx.x;  // over 64*512
    if (i >= 64 * 512) return;
    int n = i >> 9, k = i & 511;
    float w = W[(size_t)k * 64 + n];
    __nv_bfloat16 hi, lo; hl_split(w, hi, lo);
    Bt[(size_t)n * K3_L2 + k]        = hi;
    Bt[(size_t)n * K3_L2 + 512 + k]  = hi;
    Bt[(size_t)n * K3_L2 + 1024 + k] = lo;
}

// ---------------- CSR rowptr from sorted edge_src ----------------------------
__global__ void build_rowptr(const int* __restrict__ src, int E) {
    int i = blockIdx.x * blockDim.x + threadIdx.x;
    if (i >= E) return;
    int s = src[i];
    if (i == 0) {
        for (int u = 0; u <= s; u++) g_rowptr[u] = 0;
    } else {
        int p = src[i - 1];
        for (int u = p + 1; u <= s; u++) g_rowptr[u] = i;
    }
    if (i == E - 1) {
        for (int u = s + 1; u <= NN; u++) g_rowptr[u] = E;
    }
}

// ---------------- attention scores -------------------------------------------
__global__ void fscore_kernel(const float* __restrict__ Wh,
                              const float* __restrict__ a_s,
                              const float* __restrict__ a_d,
                              float* __restrict__ f1, float* __restrict__ f2) {
    int i = blockIdx.x * blockDim.x + threadIdx.x;   // i = n*8 + h
    if (i >= NN * HH) return;
    int h = i & 7;
    const float4* w  = (const float4*)(Wh + (size_t)i * DD);
    const float4* s4 = (const float4*)(a_s + h * DD);
    const float4* d4 = (const float4*)(a_d + h * DD);
    float s1 = 0.f, s2 = 0.f;
#pragma unroll
    for (int j = 0; j < 16; j++) {
        float4 wv = w[j];
        float4 x1 = s4[j];
        float4 x2 = d4[j];
        s1 += wv.x * x1.x + wv.y * x1.y + wv.z * x1.z + wv.w * x1.w;
        s2 += wv.x * x2.x + wv.y * x2.y + wv.z * x2.z + wv.w * x2.w;
    }
    f1[i] = s1;
    f2[i] = s2;
}

// ---------------- per-node softmax + SPMM + ELU -> bf16 A' layout ------------
__device__ __forceinline__ float elu_f(float x) {
    return x > 0.f ? x : (__expf(x) - 1.f);
}

__global__ __launch_bounds__(128)
void aggregate_kernel(const int* __restrict__ dst,
                      const float* __restrict__ Wh,
                      const float* __restrict__ f1,
                      const float* __restrict__ f2,
                      __nv_bfloat16* __restrict__ Aout) {  // [NPAD, 1536] = [hi|lo|hi]
    int u  = blockIdx.x;
    int t  = threadIdx.x;
    int h  = t >> 4;
    int d0 = (t & 15) << 2;

    int beg = g_rowptr[u];
    int end = g_rowptr[u + 1];

    float fu = f1[u * HH + h];

    float m = -1e30f;
    for (int e = beg; e < end; e++) {
        int v = __ldg(&dst[e]);
        float x = fu + __ldg(&f2[v * HH + h]);
        x = x > 0.f ? x : ALPHA * x;
        m = fmaxf(m, x);
    }

    float s = 0.f;
    float4 acc = make_float4(0.f, 0.f, 0.f, 0.f);
    for (int e = beg; e < end; e++) {
        int v = __ldg(&dst[e]);
        float x = fu + __ldg(&f2[v * HH + h]);
        x = x > 0.f ? x : ALPHA * x;
        float p = __expf(x - m);
        s += p;
        float4 w = *(const float4*)(Wh + (size_t)v * HD + h * DD + d0);
        acc.x = fmaf(p, w.x, acc.x);
        acc.y = fmaf(p, w.y, acc.y);
        acc.z = fmaf(p, w.z, acc.z);
        acc.w = fmaf(p, w.w, acc.w);
    }

    float inv = (end > beg) ? (1.f / s) : 0.f;
    float4 o;
    o.x = elu_f(acc.x * inv);
    o.y = elu_f(acc.y * inv);
    o.z = elu_f(acc.z * inv);
    o.w = elu_f(acc.w * inv);

    __nv_bfloat16 hx, hy, hz, hw, lx, ly, lz, lw;
    hl_split(o.x, hx, lx); hl_split(o.y, hy, ly);
    hl_split(o.z, hz, lz); hl_split(o.w, hw, lw);
    __nv_bfloat16* p = Aout + (size_t)u * K3_L2 + (h * DD + d0);
    *(__nv_bfloat162*)(p)         = __halves2bfloat162(hx, hy);
    *(__nv_bfloat162*)(p + 2)     = __halves2bfloat162(hz, hw);
    *(__nv_bfloat162*)(p + 512)   = __halves2bfloat162(lx, ly);
    *(__nv_bfloat162*)(p + 514)   = __halves2bfloat162(lz, lw);
    *(__nv_bfloat162*)(p + 1024)  = __halves2bfloat162(hx, hy);
    *(__nv_bfloat162*)(p + 1026)  = __halves2bfloat162(hz, hw);
}

// ---------------- launch ------------------------------------------------------
extern "C" void kernel_launch(void* const* d_in, const int* in_sizes, int n_in,
                              void* d_out, int out_size) {
    const float* x       = (const float*)d_in[0];
    const int*   src     = (const int*)  d_in[1];
    const int*   dst     = (const int*)  d_in[2];
    const float* W1      = (const float*)d_in[3];
    const float* a_src1  = (const float*)d_in[4];
    const float* a_dst1  = (const float*)d_in[5];
    const float* W2      = (const float*)d_in[6];
    const float* a_src2  = (const float*)d_in[7];
    const float* a_dst2  = (const float*)d_in[8];
    const float* lin_W   = (const float*)d_in[9];
    const float* lin_b   = (const float*)d_in[10];
    float* out = (float*)d_out;

    int E = in_sizes[1];

    __nv_bfloat16 *p_A1, *p_A2, *p_AL, *p_B1, *p_B2, *p_BL;
    float *p_Wh, *p_f1, *p_f2;
    cudaGetSymbolAddress((void**)&p_A1, g_A1);
    cudaGetSymbolAddress((void**)&p_A2, g_A2);
    cudaGetSymbolAddress((void**)&p_AL, g_AL);
    cudaGetSymbolAddress((void**)&p_B1, g_B1);
    cudaGetSymbolAddress((void**)&p_B2, g_B2);
    cudaGetSymbolAddress((void**)&p_BL, g_BL);
    cudaGetSymbolAddress((void**)&p_Wh, g_Wh);
    cudaGetSymbolAddress((void**)&p_f1, g_f1);
    cudaGetSymbolAddress((void**)&p_f2, g_f2);

    const int SMEM128 = 2 * 16384 + 2 * 128 * 128;  // 65536
    const int SMEM64  = 2 * 16384 + 2 * 64 * 128;   // 49152
    cudaFuncSetAttribute(mma_gemm<128>, cudaFuncAttributeMaxDynamicSharedMemorySize, SMEM128);
    cudaFuncSetAttribute(mma_gemm<64>,  cudaFuncAttributeMaxDynamicSharedMemorySize, SMEM64);

    // conversions + CSR
    conv_x   <<<(NN * 64 + 255) / 256, 256>>>(x, p_A1);
    conv_w   <<<(512 * 256 + 255) / 256, 256>>>(W1, p_B1, 256);
    conv_w   <<<(512 * 512 + 255) / 256, 256>>>(W2, p_B2, 512);
    conv_linw<<<(64 * 512 + 255) / 256, 256>>>(lin_W, p_BL);
    build_rowptr<<<(E + 255) / 256, 256>>>(src, E);

    dim3 gL(4, NPAD / 128);   // N=512 in tiles of 128
    dim3 gF(1, NPAD / 128);

    // ---- layer 1 ----
    mma_gemm<128><<<gL, 256, SMEM128>>>(p_A1, p_B1, p_Wh, nullptr, NN, K3_L1, HD);
    fscore_kernel<<<(NN * HH + 255) / 256, 256>>>(p_Wh, a_src1, a_dst1, p_f1, p_f2);
    aggregate_kernel<<<NN, 128>>>(dst, p_Wh, p_f1, p_f2, p_A2);

    // ---- layer 2 ----
    mma_gemm<128><<<gL, 256, SMEM128>>>(p_A2, p_B2, p_Wh, nullptr, NN, K3_L2, HD);
    fscore_kernel<<<(NN * HH + 255) / 256, 256>>>(p_Wh, a_src2, a_dst2, p_f1, p_f2);
    aggregate_kernel<<<NN, 128>>>(dst, p_Wh, p_f1, p_f2, p_AL);

    // ---- final linear (bias) ----
    mma_gemm<64><<<gF, 256, SMEM64>>>(p_AL, p_BL, out, lin_b, NN, K3_L2, 64);
}